// round 6
// baseline (speedup 1.0000x reference)
#include <cuda_runtime.h>
#include <math.h>
#include <stdint.h>

#define SEQ   256
#define NB    32
#define REC   16
#define EMB   32
#define VOCAB 32000
#define ROWS  (SEQ*NB)        /* 8192 */

#define BLK_M   64
#define BLK_N   512
#define NBLK_N  63                 /* ceil(32000/512) */
#define MT_PER_BLK 4               /* m-tiles per block */
#define NBLK_M  (ROWS/(BLK_M*MT_PER_BLK))   /* 32 */
#define NPART   (NBLK_N*4)         /* 252 partials per row */
#define VTHREADS 512
#define VS_STRIDE 520              /* padded n-stride (words): conflict-free */

__device__ float g_ih[ROWS*REC];
__device__ float g_hidden[ROWS*REC];
__device__ float g_part[ROWS*NPART];
__device__ float g_lse[ROWS];

/* ---- bf16 helpers ---- */
__device__ __forceinline__ uint32_t bf16x2(float lo, float hi) {
    uint32_t r;
    asm("cvt.rn.bf16x2.f32 %0, %1, %2;" : "=r"(r) : "f"(hi), "f"(lo));
    return r;
}
/* D(4xf32) += A(16x16 bf16) * B(16x8 bf16) */
__device__ __forceinline__ void mma_bf16(float* d, const uint32_t* a,
                                         uint32_t b0, uint32_t b1) {
    asm volatile(
        "mma.sync.aligned.m16n8k16.row.col.f32.bf16.bf16.f32 "
        "{%0,%1,%2,%3}, {%4,%5,%6,%7}, {%8,%9}, {%0,%1,%2,%3};\n"
        : "+f"(d[0]), "+f"(d[1]), "+f"(d[2]), "+f"(d[3])
        : "r"(a[0]), "r"(a[1]), "r"(a[2]), "r"(a[3]), "r"(b0), "r"(b1));
}

/* ---------------- kernel 1: i_h = emb[idx] @ U^T + b1 ---------------- */
__global__ void k_ih(const int* __restrict__ inp, const float* __restrict__ emb,
                     const float* __restrict__ U, const float* __restrict__ b1)
{
    int gid = blockIdx.x*blockDim.x + threadIdx.x;
    if (gid >= ROWS*REC) return;
    int row = gid >> 4;
    int r   = gid & 15;
    int idx = inp[row];
    const float4* e4 = (const float4*)(emb + (size_t)idx*EMB);
    const float4* u4 = (const float4*)(U + r*EMB);
    float acc = b1[r];
    #pragma unroll
    for (int q = 0; q < 8; q++) {
        float4 e = e4[q], u = u4[q];
        acc += e.x*u.x + e.y*u.y + e.z*u.z + e.w*u.w;
    }
    g_ih[gid] = acc;
}

/* ---------------- kernel 2: sequential recurrence (1 warp / batch) ---- */
__global__ void k_rnn(const float* __restrict__ W, const float* __restrict__ b2,
                      const float* __restrict__ h0)
{
    int b = blockIdx.x;
    int r = threadIdx.x;
    __shared__ __align__(16) float ihs[SEQ*REC];   /* 16 KB */
    __shared__ float hs[REC];

    for (int s = r; s < SEQ; s += 32) {
        const float4* src = (const float4*)(g_ih + (size_t)(s*NB + b)*REC);
        float4* dst = (float4*)(ihs + s*REC);
        dst[0] = src[0]; dst[1] = src[1]; dst[2] = src[2]; dst[3] = src[3];
    }
    float wrow[REC];
    float bias = 0.f;
    if (r < REC) {
        hs[r] = h0[r];
        #pragma unroll
        for (int k = 0; k < REC; k++) wrow[k] = W[r*REC + k];
        bias = b2[r];
    }
    __syncwarp();
    for (int s = 0; s < SEQ; s++) {
        float hn = 0.f;
        if (r < REC) {
            int row = s*NB + b;
            g_hidden[row*REC + r] = hs[r];          /* pre-update h */
            float acc = ihs[s*REC + r] + bias;
            #pragma unroll
            for (int k = 0; k < REC; k++) acc += wrow[k]*hs[k];
            hn = tanhf(acc);
        }
        __syncwarp();
        if (r < REC) hs[r] = hn;
        __syncwarp();
    }
}

/* ---------------- vocab GEMM via bf16 mma.sync m16n8k16 --------------
   WRITE=0: per-row sum-of-exp partials.  WRITE=1: out = logit - lse.
   Block: 512 thr / 16 warps; owns a 512-col V chunk (staged once as
   packed bf16x2 in shared), loops over 4 M-tiles of 64 rows.
   warp w: m-group mg = w&3 (16 rows), n-group ng = w>>2 (128 cols).
   Per n8-tile: 2 LDS + 1 MMA.                                          */
template<int WRITE>
__global__ void __launch_bounds__(VTHREADS)
k_vocab(const float* __restrict__ V, float* __restrict__ out)
{
    __shared__ __align__(16) uint32_t Vs[8*VS_STRIDE];   /* 16.6 KB */
    int tid  = threadIdx.x;
    int lane = tid & 31;
    int w    = tid >> 5;
    int mg   = w & 3;
    int ng   = w >> 2;
    int nBase = blockIdx.x * BLK_N;

    /* stage V^T packed: Vs[kp][n] = (V[n][2kp], V[n][2kp+1]) as bf16x2 */
    {
        int n  = tid;
        int gn = nBase + n;
        float4 q0, q1, q2, q3;
        if (gn < VOCAB) {
            const float4* p = (const float4*)(V + (size_t)gn*REC);
            q0 = p[0]; q1 = p[1]; q2 = p[2]; q3 = p[3];
        } else {
            q0 = q1 = q2 = q3 = make_float4(0.f,0.f,0.f,0.f);
        }
        Vs[0*VS_STRIDE + n] = bf16x2(q0.x, q0.y);
        Vs[1*VS_STRIDE + n] = bf16x2(q0.z, q0.w);
        Vs[2*VS_STRIDE + n] = bf16x2(q1.x, q1.y);
        Vs[3*VS_STRIDE + n] = bf16x2(q1.z, q1.w);
        Vs[4*VS_STRIDE + n] = bf16x2(q2.x, q2.y);
        Vs[5*VS_STRIDE + n] = bf16x2(q2.z, q2.w);
        Vs[6*VS_STRIDE + n] = bf16x2(q3.x, q3.y);
        Vs[7*VS_STRIDE + n] = bf16x2(q3.z, q3.w);
    }
    __syncthreads();

    int g = lane >> 2, c = lane & 3;
    int nCol0 = nBase + ng*128;

    for (int mt = 0; mt < MT_PER_BLK; mt++) {
        int rowBase = (blockIdx.y*MT_PER_BLK + mt) * BLK_M;
        int r0i = rowBase + mg*16 + g;
        int r1i = r0i + 8;

        /* A fragments (row-major m16k16): a0=(r0, k=2c,2c+1) a1=(r1,...)
           a2=(r0, k=2c+8,2c+9) a3=(r1, ...)                              */
        uint32_t a[4];
        {
            const float* h0p = g_hidden + (size_t)r0i*REC;
            const float* h1p = g_hidden + (size_t)r1i*REC;
            a[0] = bf16x2(h0p[2*c],     h0p[2*c+1]);
            a[1] = bf16x2(h1p[2*c],     h1p[2*c+1]);
            a[2] = bf16x2(h0p[2*c+8],   h0p[2*c+9]);
            a[3] = bf16x2(h1p[2*c+8],   h1p[2*c+9]);
        }
        float lse0 = 0.f, lse1 = 0.f;
        if (WRITE) { lse0 = g_lse[r0i]; lse1 = g_lse[r1i]; }

        float sum0 = 0.f, sum1 = 0.f;

        #pragma unroll
        for (int t = 0; t < 16; t++) {
            int nc = ng*128 + t*8;
            /* B frags (col-major k16n8): b0 = (k=2c,2c+1, n=g),
               b1 = (k=2c+8,2c+9, n=g)                                    */
            uint32_t b0 = Vs[ c     *VS_STRIDE + nc + g];
            uint32_t b1 = Vs[(c + 4)*VS_STRIDE + nc + g];
            float d[4] = {0.f, 0.f, 0.f, 0.f};
            mma_bf16(d, a, b0, b1);

            int gcol = nCol0 + t*8 + 2*c;   /* pair-aligned; VOCAB%8==0 */
            if (WRITE) {
                if (gcol < VOCAB) {
                    *(float2*)(out + (size_t)r0i*VOCAB + gcol) =
                        make_float2(d[0]-lse0, d[1]-lse0);
                    *(float2*)(out + (size_t)r1i*VOCAB + gcol) =
                        make_float2(d[2]-lse1, d[3]-lse1);
                }
            } else {
                if (gcol < VOCAB) {
                    sum0 += __expf(d[0]) + __expf(d[1]);
                    sum1 += __expf(d[2]) + __expf(d[3]);
                }
            }
        }

        if (!WRITE) {
            sum0 += __shfl_xor_sync(0xffffffffu, sum0, 1);
            sum0 += __shfl_xor_sync(0xffffffffu, sum0, 2);
            sum1 += __shfl_xor_sync(0xffffffffu, sum1, 1);
            sum1 += __shfl_xor_sync(0xffffffffu, sum1, 2);
            if (c == 0) {
                int pi = blockIdx.x*4 + ng;
                g_part[(size_t)r0i*NPART + pi] = sum0;
                g_part[(size_t)r1i*NPART + pi] = sum1;
            }
        }
    }
}

/* ---------------- lse[row] = log(sum of 252 partials) ---------------- */
__global__ void k_lse()
{
    int row = blockIdx.x*blockDim.x + threadIdx.x;
    if (row >= ROWS) return;
    const float4* p = (const float4*)(g_part + (size_t)row*NPART);
    float s = 0.f;
    #pragma unroll
    for (int i = 0; i < NPART/4; i++) {
        float4 v = p[i];
        s += (v.x + v.y) + (v.z + v.w);
    }
    g_lse[row] = logf(s);
}

extern "C" void kernel_launch(void* const* d_in, const int* in_sizes, int n_in,
                              void* d_out, int out_size)
{
    const int*   inp = (const int*)d_in[0];
    const float* emb = (const float*)d_in[1];
    const float* U   = (const float*)d_in[2];
    const float* W   = (const float*)d_in[3];
    const float* V   = (const float*)d_in[4];
    const float* b1  = (const float*)d_in[5];
    const float* b2  = (const float*)d_in[6];
    const float* h0  = (const float*)d_in[7];
    float* out = (float*)d_out;

    k_ih<<<(ROWS*REC + 255)/256, 256>>>(inp, emb, U, b1);
    k_rnn<<<NB, 32>>>(W, b2, h0);
    k_vocab<0><<<dim3(NBLK_N, NBLK_M), VTHREADS>>>(V, nullptr);
    k_lse<<<(ROWS + 255)/256, 256>>>();
    k_vocab<1><<<dim3(NBLK_N, NBLK_M), VTHREADS>>>(V, out);
}